// round 5
// baseline (speedup 1.0000x reference)
#include <cuda_runtime.h>
#include <math.h>

#define G     15
#define NB    4
#define NPTS  300000
#define PPC   (NB*NPTS)

// padded grid: [B][12][19][19][21-row] ; per-channel stride 7584 (16B aligned)
#define PD    19
#define ROWS  21
#define CSTR  7584
#define BSTR  (12*CSTR)
#define GRIDN (NB*BSTR)

typedef unsigned long long ull;

__device__ float  g_grid[GRIDN];
__device__ float  g_bufA[NB*8*512];
__device__ float  g_bufB[NB*8*512];
__device__ float2 g_slots0[128];   // [oc][b*4+odp]
__device__ float2 g_slots1[128];

// ---------------- packed f32x2 helpers --------------------------------------
__device__ __forceinline__ ull pack2(float lo, float hi){
    ull r; asm("mov.b64 %0, {%1,%2};" : "=l"(r) : "f"(lo), "f"(hi)); return r;
}
__device__ __forceinline__ void unpack2(ull v, float& lo, float& hi){
    asm("mov.b64 {%0,%1}, %2;" : "=f"(lo), "=f"(hi) : "l"(v));
}
__device__ __forceinline__ ull fma2(ull a, ull b, ull c){
    ull d; asm("fma.rn.f32x2 %0, %1, %2, %3;" : "=l"(d) : "l"(a), "l"(b), "l"(c)); return d;
}
__device__ __forceinline__ float eluf(float x){ return x > 0.f ? x : (__expf(x)-1.f); }
__device__ __forceinline__ ull elu2(ull v){
    float lo, hi; unpack2(v, lo, hi);
    return pack2(eluf(lo), eluf(hi));
}

// two-value block reduction (128 threads) via shuffle + tiny smem
__device__ __forceinline__ float2 blockRed2(float a, float b, float* sm, int t){
    #pragma unroll
    for (int o=16;o;o>>=1){
        a += __shfl_xor_sync(0xffffffffu, a, o);
        b += __shfl_xor_sync(0xffffffffu, b, o);
    }
    if ((t&31)==0){ sm[(t>>5)*2]=a; sm[(t>>5)*2+1]=b; }
    __syncthreads();
    float2 r;
    r.x = sm[0]+sm[2]+sm[4]+sm[6];
    r.y = sm[1]+sm[3]+sm[5]+sm[7];
    return r;
}

// ---------------------------------------------------------------------------
__global__ void zero_grid_kernel(){
    int i = blockIdx.x*blockDim.x + threadIdx.x;
    if (i < GRIDN) g_grid[i] = 0.f;
}

// ---------------- point stage: disty -> MLP (f32x2) -> scatter-max ----------
__device__ __forceinline__ void disty_one(float px, float py, float pz,
                                          float f[12], int& cellpad)
{
    const float CLIPHI = 15.0f - 1e-4f;
    float cx = floorf(fminf(fmaxf(px,0.f), CLIPHI));
    float cy = floorf(fminf(fmaxf(py,0.f), CLIPHI));
    float cz = floorf(fminf(fmaxf(pz,0.f), CLIPHI));
    float ocx = px-(cx+0.5f), ocy = py-(cy+0.5f), ocz = pz-(cz+0.5f);
    float olx = px-cx,        oly = py-cy,        olz = pz-cz;
    float oux = px-(cx+1.f),  ouy = py-(cy+1.f),  ouz = pz-(cz+1.f);
    f[0]=ocx; f[1]=ocy; f[2]=ocz;
    f[3]=olx; f[4]=oly; f[5]=olz;
    f[6]=oux; f[7]=ouy; f[8]=ouz;
    f[9]  = sqrtf(ocx*ocx+ocy*ocy+ocz*ocz);
    f[10] = sqrtf(olx*olx+oly*oly+olz*olz);
    f[11] = sqrtf(oux*oux+ouy*ouy+ouz*ouz);
    cellpad = ((int)cx+2)*(PD*ROWS) + ((int)cy+2)*ROWS + ((int)cz+2);
}

__global__ void __launch_bounds__(256,2)
point_kernel(const float* __restrict__ P0, const float* __restrict__ P1,
             const float* __restrict__ P2,
             const float* __restrict__ W1, const float* __restrict__ B1,
             const float* __restrict__ W2, const float* __restrict__ B2,
             const float* __restrict__ W3, const float* __restrict__ B3)
{
    __shared__ __align__(16) ull pW1[192], pW2[256], pW3[64];
    __shared__ ull pb1[16], pb2[16], pb3[4];
    int t = threadIdx.x;
    for (int i=t;i<192;i+=256) pW1[i]=pack2(W1[i],W1[i]);
    for (int i=t;i<256;i+=256) pW2[i]=pack2(W2[i],W2[i]);
    for (int i=t;i<64; i+=256) pW3[i]=pack2(W3[i],W3[i]);
    if (t<16){ pb1[t]=pack2(B1[t],B1[t]); pb2[t]=pack2(B2[t],B2[t]); }
    if (t<4)  pb3[t]=pack2(B3[t],B3[t]);
    __syncthreads();

    const float* pts = (blockIdx.y==0) ? P0 : (blockIdx.y==1 ? P1 : P2);
    int chan = blockIdx.y*4;

    long tid = (long)blockIdx.x*256 + t;
    long p0  = tid*2;
    if (p0 >= PPC) return;

    const float2* v = (const float2*)(pts + p0*3);
    float2 f0=v[0], f1=v[1], f2=v[2];
    float fa[12], fb[12]; int ca, cb;
    disty_one(f0.x, f0.y, f1.x, fa, ca);
    disty_one(f1.y, f2.x, f2.y, fb, cb);

    ull X[12];
    #pragma unroll
    for (int k=0;k<12;k++) X[k]=pack2(fa[k],fb[k]);

    ull H[16];
    #pragma unroll
    for (int j=0;j<16;j+=2){
        ull a0=pb1[j], a1=pb1[j+1];
        #pragma unroll
        for (int k=0;k<12;k++){
            ulonglong2 w = *(const ulonglong2*)&pW1[k*16+j];
            a0 = fma2(X[k], w.x, a0);
            a1 = fma2(X[k], w.y, a1);
        }
        H[j]   = elu2(a0);
        H[j+1] = elu2(a1);
    }

    ull H2[16];
    #pragma unroll
    for (int j=0;j<16;j+=2){
        ull a0=pb2[j], a1=pb2[j+1];
        #pragma unroll
        for (int k=0;k<16;k++){
            ulonglong2 w = *(const ulonglong2*)&pW2[k*16+j];
            a0 = fma2(H[k], w.x, a0);
            a1 = fma2(H[k], w.y, a1);
        }
        H2[j]   = elu2(a0);
        H2[j+1] = elu2(a1);
    }

    int b = (int)(p0 / NPTS);
    int baseA = b*BSTR + chan*CSTR + ca;
    int baseB = b*BSTR + chan*CSTR + cb;
    #pragma unroll
    for (int j=0;j<4;j++){
        ull a = pb3[j];
        #pragma unroll
        for (int k=0;k<16;k++) a = fma2(H2[k], pW3[k*4+j], a);
        float v0, v1; unpack2(a, v0, v1);
        // pre-read filter: most updates lose; skip the atomic when provably so
        if (v0 > 0.f){
            int* p = (int*)&g_grid[baseA + j*CSTR];
            if (v0 > __int_as_float(*p)) atomicMax(p, __float_as_int(v0));
        }
        if (v1 > 0.f){
            int* p = (int*)&g_grid[baseB + j*CSTR];
            if (v1 > __int_as_float(*p)) atomicMax(p, __float_as_int(v1));
        }
    }
}

// ---------------- conv1: 12->8, k5, s2, p2 ; grid (oc8, b4, odp4) -----------
// block covers 2 output d-planes; smem holds the 7 needed padded input planes
// per channel. 1 output/thread (128 thr = 2 odl x 64 hw). Bias cancels in BN.
#define C1_CH   2808                       // floats per channel slice (702 f4)
#define C1_SMEM ((12*C1_CH + 1500 + 8)*4)  // ~140.8 KB dynamic
__global__ void conv1_kernel(const float* __restrict__ w)
{
    extern __shared__ float dyn[];
    float* sCh  = dyn;                // [12][2808]
    float* wsm  = dyn + 12*C1_CH;     // [oc's 12*125]
    float* sred = wsm + 1500;

    int oc = blockIdx.x, b = blockIdx.y, odp = blockIdx.z;
    int t = threadIdx.x;
    int odl = t>>6, hw = t&63, oh = hw>>3, ow = hw&7;
    int od = odp*2 + odl;

    // copy d-slice [4odp .. 4odp+6] planes of each channel (f4, aligned down)
    int g0   = 4*odp*399;             // first float needed within channel
    int s0   = g0 >> 2;               // f4 start (floor)
    int off0 = s0 << 2;
    int nf4  = ((g0 + 2793 + 3) >> 2) - s0;   // <= 700
    for (int ic=0; ic<12; ic++){
        const float4* src = (const float4*)(g_grid + (b*12+ic)*CSTR);
        float4* dst = (float4*)(sCh + ic*C1_CH);
        for (int j=t; j<nf4; j+=128) dst[j] = src[s0+j];
    }
    for (int i=t; i<1500; i+=128) wsm[i] = w[oc*1500 + i];
    __syncthreads();

    float a0=0.f, a1=0.f, a2=0.f, a3=0.f, a4=0.f;
    for (int ic=0; ic<12; ic++){
        const float* cb = sCh + ic*C1_CH - off0;
        const float* wb = wsm + ic*125;
        #pragma unroll 1
        for (int kd=0; kd<5; kd++){
            const float* p  = cb + (2*od+kd)*399 + (2*oh)*21 + 2*ow;
            const float* wr = wb + kd*25;
            #pragma unroll
            for (int kh=0; kh<5; kh++){
                const float* q = p + kh*21;
                a0 += q[0]*wr[kh*5+0];
                a1 += q[1]*wr[kh*5+1];
                a2 += q[2]*wr[kh*5+2];
                a3 += q[3]*wr[kh*5+3];
                a4 += q[4]*wr[kh*5+4];
            }
        }
    }
    float acc = (a0+a1)+(a2+a3)+a4;

    g_bufA[b*4096 + oc*512 + od*64 + hw] = acc;
    float2 r = blockRed2(acc, acc*acc, sred, t);
    if (t==0) g_slots0[oc*16 + b*4 + odp] = r;
}

// ---------------- convs 2..7: fused input-BN+ELU + conv + stats -------------
// grid (oc8, b4, odp4), 128 thr, 1 output/thread. smem: 6-plane d-slice.
__global__ void convs_kernel(int dir, const float* __restrict__ w,
                             const float* __restrict__ gin, const float* __restrict__ bin)
{
    __shared__ float sIn[8*6*144];    // [ic][dd][12][12], halo-zeroed
    __shared__ float wsm[1000];
    __shared__ float sSc[8], sSh[8], sred[8];

    const float*  rin  = dir ? g_bufB   : g_bufA;
    float*        rout = dir ? g_bufA   : g_bufB;
    const float2* sin_ = dir ? g_slots1 : g_slots0;
    float2*       sout = dir ? g_slots0 : g_slots1;

    int oc = blockIdx.x, b = blockIdx.y, odp = blockIdx.z;
    int t = threadIdx.x;
    int odl = t>>6, hw = t&63, oh = hw>>3, ow = hw&7;
    int od = odp*2 + odl;

    if (t < 8){
        float sx=0.f, sy=0.f;
        #pragma unroll
        for (int q=0;q<16;q++){ float2 p = sin_[t*16+q]; sx+=p.x; sy+=p.y; }
        float m  = sx*(1.f/2048.f);
        float vr = sy*(1.f/2048.f) - m*m;
        float sc = gin[t]*rsqrtf(vr + 1e-5f);
        sSc[t]=sc; sSh[t]=bin[t]-m*sc;
    }
    float4 z4 = make_float4(0.f,0.f,0.f,0.f);
    for (int i=t;i<1728;i+=128) ((float4*)sIn)[i] = z4;
    for (int i=t;i<1000;i+=128) wsm[i] = w[oc*1000 + i];
    __syncthreads();

    // interior fill with BN+ELU: items = 8ic x 6dd x 8h x 2half = 768
    for (int i=t;i<768;i+=128){
        int half = i&1, h = (i>>1)&7, dd = (i>>4)%6, ic = i/96;
        int id = odp*2 - 2 + dd;
        if ((unsigned)id < 8u){
            float4 v = *(const float4*)(rin + b*4096 + ic*512 + id*64 + h*8 + half*4);
            float sc = sSc[ic], sh = sSh[ic];
            float* d = sIn + ic*864 + dd*144 + (h+2)*12 + 2 + half*4;
            d[0]=eluf(v.x*sc+sh); d[1]=eluf(v.y*sc+sh);
            d[2]=eluf(v.z*sc+sh); d[3]=eluf(v.w*sc+sh);
        }
    }
    __syncthreads();

    float a0=0.f, a1=0.f, a2=0.f, a3=0.f, a4=0.f;
    #pragma unroll 1
    for (int ic=0; ic<8; ic++){
        const float* cb = sIn + ic*864;
        const float* wb = wsm + ic*125;
        #pragma unroll 1
        for (int kd=0; kd<5; kd++){
            const float* p  = cb + (odl+kd)*144 + oh*12 + ow;
            const float* wr = wb + kd*25;
            #pragma unroll
            for (int kh=0; kh<5; kh++){
                const float* q = p + kh*12;
                a0 += q[0]*wr[kh*5+0];
                a1 += q[1]*wr[kh*5+1];
                a2 += q[2]*wr[kh*5+2];
                a3 += q[3]*wr[kh*5+3];
                a4 += q[4]*wr[kh*5+4];
            }
        }
    }
    float acc = (a0+a1)+(a2+a3)+a4;

    rout[b*4096 + oc*512 + od*64 + hw] = acc;
    float2 r = blockRed2(acc, acc*acc, sred, t);
    if (t==0) sout[oc*16 + b*4 + odp] = r;
}

// ---------------- final BN+ELU on layer-7 raw output ------------------------
__global__ void finalbn_kernel(float* __restrict__ out,
                               const float* __restrict__ gin, const float* __restrict__ bin)
{
    int c = blockIdx.x, t = threadIdx.x;   // 8 blocks x 256
    float sx=0.f, sy=0.f;
    #pragma unroll
    for (int q=0;q<16;q++){ float2 p = g_slots0[c*16+q]; sx+=p.x; sy+=p.y; }
    float m  = sx*(1.f/2048.f);
    float vr = sy*(1.f/2048.f) - m*m;
    float sc = gin[c]*rsqrtf(vr + 1e-5f);
    float sh = bin[c]-m*sc;
    #pragma unroll
    for (int r=0;r<8;r++){
        int e = t + r*256;
        int b = e>>9, sp = e&511;
        float v = g_bufA[b*4096 + c*512 + sp];
        out[(b*8+c)*512 + sp] = eluf(v*sc+sh);
    }
}

// ---------------------------------------------------------------------------
extern "C" void kernel_launch(void* const* d_in, const int* in_sizes, int n_in,
                              void* d_out, int out_size)
{
    const float* goals       = (const float*)d_in[0];
    const float* inputs      = (const float*)d_in[1];
    const float* backgrounds = (const float*)d_in[2];
    const float* W1 = (const float*)d_in[3];
    const float* b1 = (const float*)d_in[4];
    const float* W2 = (const float*)d_in[5];
    const float* b2 = (const float*)d_in[6];
    const float* W3 = (const float*)d_in[7];
    const float* b3 = (const float*)d_in[8];
    const float* conv1_w = (const float*)d_in[9];
    const float* bn1_g   = (const float*)d_in[11];
    const float* bn1_b   = (const float*)d_in[12];
    const float* convs_w = (const float*)d_in[13];
    const float* bns_g   = (const float*)d_in[15];
    const float* bns_b   = (const float*)d_in[16];
    float* out = (float*)d_out;

    cudaFuncSetAttribute(conv1_kernel, cudaFuncAttributeMaxDynamicSharedMemorySize, C1_SMEM);

    zero_grid_kernel<<<(GRIDN+255)/256, 256>>>();

    dim3 pg((PPC/2 + 255)/256, 3);
    point_kernel<<<pg,256>>>(inputs, goals, backgrounds, W1,b1,W2,b2,W3,b3);

    dim3 cg(8,4,4);
    conv1_kernel<<<cg,128,C1_SMEM>>>(conv1_w);

    convs_kernel<<<cg,128>>>(0, convs_w,         bn1_g,    bn1_b);
    convs_kernel<<<cg,128>>>(1, convs_w +  8000, bns_g,    bns_b);
    convs_kernel<<<cg,128>>>(0, convs_w + 16000, bns_g+8,  bns_b+8);
    convs_kernel<<<cg,128>>>(1, convs_w + 24000, bns_g+16, bns_b+16);
    convs_kernel<<<cg,128>>>(0, convs_w + 32000, bns_g+24, bns_b+24);
    convs_kernel<<<cg,128>>>(1, convs_w + 40000, bns_g+32, bns_b+32);

    finalbn_kernel<<<8,256>>>(out, bns_g+40, bns_b+40);
}

// round 7
// speedup vs baseline: 1.0950x; 1.0950x over previous
#include <cuda_runtime.h>
#include <math.h>

#define G     15
#define NB    4
#define NPTS  300000
#define PPC   (NB*NPTS)

// padded grid: [B][12][19][19][21-row] ; per-channel stride 7584
#define PD    19
#define ROWS  21
#define CSTR  7584
#define BSTR  (12*CSTR)
#define GRIDN (NB*BSTR)

typedef unsigned long long ull;

__device__ float  g_grid[GRIDN];
__device__ float  g_bufA[NB*8*512];
__device__ float  g_bufB[NB*8*512];
__device__ float2 g_slots0[128];   // [oc][b*4+odp]
__device__ float2 g_slots1[128];
__device__ unsigned g_bar_count = 0;
__device__ unsigned g_bar_phase = 0;

// ---------------- packed f32x2 helpers --------------------------------------
__device__ __forceinline__ ull pack2(float lo, float hi){
    ull r; asm("mov.b64 %0, {%1,%2};" : "=l"(r) : "f"(lo), "f"(hi)); return r;
}
__device__ __forceinline__ void unpack2(ull v, float& lo, float& hi){
    asm("mov.b64 {%0,%1}, %2;" : "=f"(lo), "=f"(hi) : "l"(v));
}
__device__ __forceinline__ ull fma2(ull a, ull b, ull c){
    ull d; asm("fma.rn.f32x2 %0, %1, %2, %3;" : "=l"(d) : "l"(a), "l"(b), "l"(c)); return d;
}
__device__ __forceinline__ float eluf(float x){ return x > 0.f ? x : (__expf(x)-1.f); }
__device__ __forceinline__ ull elu2(ull v){
    float lo, hi; unpack2(v, lo, hi);
    return pack2(eluf(lo), eluf(hi));
}

// software grid barrier (phase ticket; monotonic across launches -> replay-safe)
__device__ __forceinline__ void gridBar(int t){
    __syncthreads();
    if (t==0){
        unsigned my = *((volatile unsigned*)&g_bar_phase);
        __threadfence();
        unsigned old = atomicAdd(&g_bar_count, 1u);
        if (old == 127u){
            g_bar_count = 0;
            __threadfence();
            atomicExch(&g_bar_phase, my + 1u);
        } else {
            while (*((volatile unsigned*)&g_bar_phase) == my) { }
        }
        __threadfence();
    }
    __syncthreads();
}

// two-value block reduction (128 threads)
__device__ __forceinline__ float2 blockRed2(float a, float b, float* sm, int t){
    #pragma unroll
    for (int o=16;o;o>>=1){
        a += __shfl_xor_sync(0xffffffffu, a, o);
        b += __shfl_xor_sync(0xffffffffu, b, o);
    }
    if ((t&31)==0){ sm[(t>>5)*2]=a; sm[(t>>5)*2+1]=b; }
    __syncthreads();
    float2 r;
    r.x = sm[0]+sm[2]+sm[4]+sm[6];
    r.y = sm[1]+sm[3]+sm[5]+sm[7];
    return r;
}

// ---------------------------------------------------------------------------
__global__ void zero_grid_kernel(){
    int i = blockIdx.x*blockDim.x + threadIdx.x;
    if (i < GRIDN) g_grid[i] = 0.f;
}

// ---------------- point stage: disty -> MLP (f32x2) -> scatter-max ----------
__device__ __forceinline__ void disty_one(float px, float py, float pz,
                                          float f[12], int& cellpad)
{
    const float CLIPHI = 15.0f - 1e-4f;
    float cx = floorf(fminf(fmaxf(px,0.f), CLIPHI));
    float cy = floorf(fminf(fmaxf(py,0.f), CLIPHI));
    float cz = floorf(fminf(fmaxf(pz,0.f), CLIPHI));
    float ocx = px-(cx+0.5f), ocy = py-(cy+0.5f), ocz = pz-(cz+0.5f);
    float olx = px-cx,        oly = py-cy,        olz = pz-cz;
    float oux = px-(cx+1.f),  ouy = py-(cy+1.f),  ouz = pz-(cz+1.f);
    f[0]=ocx; f[1]=ocy; f[2]=ocz;
    f[3]=olx; f[4]=oly; f[5]=olz;
    f[6]=oux; f[7]=ouy; f[8]=ouz;
    f[9]  = sqrtf(ocx*ocx+ocy*ocy+ocz*ocz);
    f[10] = sqrtf(olx*olx+oly*oly+olz*olz);
    f[11] = sqrtf(oux*oux+ouy*ouy+ouz*ouz);
    cellpad = ((int)cx+2)*(PD*ROWS) + ((int)cy+2)*ROWS + ((int)cz+2);
}

__global__ void __launch_bounds__(256,2)
point_kernel(const float* __restrict__ P0, const float* __restrict__ P1,
             const float* __restrict__ P2,
             const float* __restrict__ W1, const float* __restrict__ B1,
             const float* __restrict__ W2, const float* __restrict__ B2,
             const float* __restrict__ W3, const float* __restrict__ B3)
{
    __shared__ __align__(16) ull pW1[192], pW2[256], pW3[64];
    __shared__ ull pb1[16], pb2[16], pb3[4];
    int t = threadIdx.x;
    for (int i=t;i<192;i+=256) pW1[i]=pack2(W1[i],W1[i]);
    for (int i=t;i<256;i+=256) pW2[i]=pack2(W2[i],W2[i]);
    for (int i=t;i<64; i+=256) pW3[i]=pack2(W3[i],W3[i]);
    if (t<16){ pb1[t]=pack2(B1[t],B1[t]); pb2[t]=pack2(B2[t],B2[t]); }
    if (t<4)  pb3[t]=pack2(B3[t],B3[t]);
    __syncthreads();

    const float* pts = (blockIdx.y==0) ? P0 : (blockIdx.y==1 ? P1 : P2);
    int chan = blockIdx.y*4;

    long tid = (long)blockIdx.x*256 + t;
    long p0  = tid*2;
    if (p0 >= PPC) return;

    const float2* v = (const float2*)(pts + p0*3);
    float2 f0=v[0], f1=v[1], f2=v[2];
    float fa[12], fb[12]; int ca, cb;
    disty_one(f0.x, f0.y, f1.x, fa, ca);
    disty_one(f1.y, f2.x, f2.y, fb, cb);

    ull X[12];
    #pragma unroll
    for (int k=0;k<12;k++) X[k]=pack2(fa[k],fb[k]);

    ull H[16];
    #pragma unroll
    for (int j=0;j<16;j+=2){
        ull a0=pb1[j], a1=pb1[j+1];
        #pragma unroll
        for (int k=0;k<12;k++){
            ulonglong2 w = *(const ulonglong2*)&pW1[k*16+j];
            a0 = fma2(X[k], w.x, a0);
            a1 = fma2(X[k], w.y, a1);
        }
        H[j]   = elu2(a0);
        H[j+1] = elu2(a1);
    }

    ull H2[16];
    #pragma unroll
    for (int j=0;j<16;j+=2){
        ull a0=pb2[j], a1=pb2[j+1];
        #pragma unroll
        for (int k=0;k<16;k++){
            ulonglong2 w = *(const ulonglong2*)&pW2[k*16+j];
            a0 = fma2(H[k], w.x, a0);
            a1 = fma2(H[k], w.y, a1);
        }
        H2[j]   = elu2(a0);
        H2[j+1] = elu2(a1);
    }

    int b = (int)(p0 / NPTS);
    int baseA = b*BSTR + chan*CSTR + ca;
    int baseB = b*BSTR + chan*CSTR + cb;
    #pragma unroll
    for (int j=0;j<4;j++){
        ull a = pb3[j];
        #pragma unroll
        for (int k=0;k<16;k++) a = fma2(H2[k], pW3[k*4+j], a);
        float v0, v1; unpack2(a, v0, v1);
        if (v0 > 0.f) atomicMax((int*)&g_grid[baseA + j*CSTR], __float_as_int(v0));
        if (v1 > 0.f) atomicMax((int*)&g_grid[baseB + j*CSTR], __float_as_int(v1));
    }
}

// ---------------- fused conv stack: conv1 + 6x(BN+ELU+conv) + final BN ------
// grid 128 = (oc8, b4, odp4), 128 threads, software grid barrier between layers
#define C1_CH   2808
#define FS_SMEM ((12*C1_CH + 1500 + 16)*4)   // ~141 KB (conv1 phase high-water)
__global__ void __launch_bounds__(128,1)
conv_stack_kernel(const float* __restrict__ w1,
                  const float* __restrict__ wS,
                  const float* __restrict__ bn1_g, const float* __restrict__ bn1_b,
                  const float* __restrict__ bns_g, const float* __restrict__ bns_b,
                  float* __restrict__ outp)
{
    extern __shared__ float dyn[];
    // conv1 phase layout
    float* sCh  = dyn;                 // [12][2808]
    float* w1sm = dyn + 12*C1_CH;      // 1500
    float* sred = w1sm + 1500;         // 16
    // convs phase layout (reuses same memory)
    float* sIn  = dyn;                 // [8][6][12][12] = 6912
    float* wsm  = dyn + 6912;          // 1000
    float* sSc  = wsm + 1000;          // 8
    float* sSh  = sSc + 8;             // 8

    int oc = blockIdx.x & 7, b = (blockIdx.x>>3) & 3, odp = blockIdx.x>>5;
    int t = threadIdx.x;
    int odl = t>>6, hw = t&63, oh = hw>>3, ow = hw&7;
    int od = odp*2 + odl;

    // ================= conv1: 12->8, k5, s2, p2 =================
    {
        int g0   = 4*odp*399;
        int s0   = g0 >> 2;
        int off0 = s0 << 2;
        int nf4  = ((g0 + 2793 + 3) >> 2) - s0;
        for (int ic=0; ic<12; ic++){
            const float4* src = (const float4*)(g_grid + (b*12+ic)*CSTR);
            float4* dst = (float4*)(sCh + ic*C1_CH);
            for (int j=t; j<nf4; j+=128) dst[j] = src[s0+j];
        }
        for (int i=t; i<1500; i+=128) w1sm[i] = w1[oc*1500 + i];
        __syncthreads();

        float a0=0.f, a1=0.f, a2=0.f, a3=0.f, a4=0.f;
        for (int ic=0; ic<12; ic++){
            const float* cb = sCh + ic*C1_CH - off0;
            const float* wb = w1sm + ic*125;
            #pragma unroll 1
            for (int kd=0; kd<5; kd++){
                const float* p  = cb + (2*od+kd)*399 + (2*oh)*21 + 2*ow;
                const float* wr = wb + kd*25;
                #pragma unroll
                for (int kh=0; kh<5; kh++){
                    const float* q = p + kh*21;
                    a0 += q[0]*wr[kh*5+0];
                    a1 += q[1]*wr[kh*5+1];
                    a2 += q[2]*wr[kh*5+2];
                    a3 += q[3]*wr[kh*5+3];
                    a4 += q[4]*wr[kh*5+4];
                }
            }
        }
        float acc1 = (a0+a1)+(a2+a3)+a4;
        g_bufA[b*4096 + oc*512 + od*64 + hw] = acc1;
        float2 r = blockRed2(acc1, acc1*acc1, sred, t);
        if (t==0) g_slots0[oc*16 + b*4 + odp] = r;
    }
    gridBar(t);

    // ================= 6x (input BN+ELU -> conv 8->8 k5 p2) =================
    float acc = 0.f;
    for (int L=0; L<6; L++){
        int dir = L & 1;
        const float*  rin  = dir ? g_bufB   : g_bufA;
        float*        rout = dir ? g_bufA   : g_bufB;
        const float2* sinp = dir ? g_slots1 : g_slots0;
        float2*       sout = dir ? g_slots0 : g_slots1;
        const float*  gin  = (L==0) ? bn1_g : (bns_g + (L-1)*8);
        const float*  bin  = (L==0) ? bn1_b : (bns_b + (L-1)*8);
        const float*  w    = wS + L*8000;

        if (t < 8){
            float sx=0.f, sy=0.f;
            #pragma unroll
            for (int q=0;q<16;q++){ float2 p = sinp[t*16+q]; sx+=p.x; sy+=p.y; }
            float m  = sx*(1.f/2048.f);
            float vr = sy*(1.f/2048.f) - m*m;
            float sc = gin[t]*rsqrtf(vr + 1e-5f);
            sSc[t]=sc; sSh[t]=bin[t]-m*sc;
        }
        float4 z4 = make_float4(0.f,0.f,0.f,0.f);
        for (int i=t;i<1728;i+=128) ((float4*)sIn)[i] = z4;
        for (int i=t;i<1000;i+=128) wsm[i] = w[oc*1000 + i];
        __syncthreads();

        for (int i=t;i<768;i+=128){
            int half = i&1, h = (i>>1)&7, dd = (i>>4)%6, ic = i/96;
            int id = odp*2 - 2 + dd;
            if ((unsigned)id < 8u){
                float4 v = *(const float4*)(rin + b*4096 + ic*512 + id*64 + h*8 + half*4);
                float sc = sSc[ic], sh = sSh[ic];
                float* d = sIn + ic*864 + dd*144 + (h+2)*12 + 2 + half*4;
                d[0]=eluf(v.x*sc+sh); d[1]=eluf(v.y*sc+sh);
                d[2]=eluf(v.z*sc+sh); d[3]=eluf(v.w*sc+sh);
            }
        }
        __syncthreads();

        float a0=0.f, a1=0.f, a2=0.f, a3=0.f, a4=0.f;
        #pragma unroll 1
        for (int ic=0; ic<8; ic++){
            const float* cb = sIn + ic*864;
            const float* wb = wsm + ic*125;
            #pragma unroll 1
            for (int kd=0; kd<5; kd++){
                const float* p  = cb + (odl+kd)*144 + oh*12 + ow;
                const float* wr = wb + kd*25;
                #pragma unroll
                for (int kh=0; kh<5; kh++){
                    const float* q = p + kh*12;
                    a0 += q[0]*wr[kh*5+0];
                    a1 += q[1]*wr[kh*5+1];
                    a2 += q[2]*wr[kh*5+2];
                    a3 += q[3]*wr[kh*5+3];
                    a4 += q[4]*wr[kh*5+4];
                }
            }
        }
        acc = (a0+a1)+(a2+a3)+a4;

        rout[b*4096 + oc*512 + od*64 + hw] = acc;
        __syncthreads();
        {
            float2 r = blockRed2(acc, acc*acc, sSc, t);  // reuse sSc/sSh region
            if (t==0) sout[oc*16 + b*4 + odp] = r;
        }
        gridBar(t);
    }

    // ================= final BN+ELU from live accumulator ===================
    // last layer (L=5, dir=1) wrote its stats to slots0
    float sx=0.f, sy=0.f;
    #pragma unroll
    for (int q=0;q<16;q++){ float2 p = g_slots0[oc*16+q]; sx+=p.x; sy+=p.y; }
    float m  = sx*(1.f/2048.f);
    float vr = sy*(1.f/2048.f) - m*m;
    float sc = bns_g[40+oc]*rsqrtf(vr + 1e-5f);
    float sh = bns_b[40+oc]-m*sc;
    outp[(b*8+oc)*512 + od*64 + hw] = eluf(acc*sc+sh);
}

// ---------------------------------------------------------------------------
extern "C" void kernel_launch(void* const* d_in, const int* in_sizes, int n_in,
                              void* d_out, int out_size)
{
    const float* goals       = (const float*)d_in[0];
    const float* inputs      = (const float*)d_in[1];
    const float* backgrounds = (const float*)d_in[2];
    const float* W1 = (const float*)d_in[3];
    const float* b1 = (const float*)d_in[4];
    const float* W2 = (const float*)d_in[5];
    const float* b2 = (const float*)d_in[6];
    const float* W3 = (const float*)d_in[7];
    const float* b3 = (const float*)d_in[8];
    const float* conv1_w = (const float*)d_in[9];
    const float* bn1_g   = (const float*)d_in[11];
    const float* bn1_b   = (const float*)d_in[12];
    const float* convs_w = (const float*)d_in[13];
    const float* bns_g   = (const float*)d_in[15];
    const float* bns_b   = (const float*)d_in[16];
    float* out = (float*)d_out;

    cudaFuncSetAttribute(conv_stack_kernel, cudaFuncAttributeMaxDynamicSharedMemorySize, FS_SMEM);

    zero_grid_kernel<<<(GRIDN+255)/256, 256>>>();

    dim3 pg((PPC/2 + 255)/256, 3);
    point_kernel<<<pg,256>>>(inputs, goals, backgrounds, W1,b1,W2,b2,W3,b3);

    conv_stack_kernel<<<128,128,FS_SMEM>>>(conv1_w, convs_w, bn1_g, bn1_b,
                                           bns_g, bns_b, out);
}

// round 8
// speedup vs baseline: 1.3923x; 1.2716x over previous
#include <cuda_runtime.h>
#include <math.h>

#define G     15
#define NB    4
#define NPTS  300000
#define PPC   (NB*NPTS)

// padded grid: [B][12][19 planes][19 rows][24 cols]; aligned rows
#define PLANE 456                  // 19*24
#define CSTR  8672                 // 19*456=8664 padded to /16B
#define BSTR  (12*CSTR)
#define GRIDN (NB*BSTR)            // 416256

typedef unsigned long long ull;

__device__ float  g_grid[GRIDN];
__device__ float  g_bufA[NB*8*512];
__device__ float  g_bufB[NB*8*512];
__device__ float2 g_slots0[128];
__device__ float2 g_slots1[128];
__device__ unsigned g_bar_count = 0;
__device__ unsigned g_bar_phase = 0;

// ---------------- helpers ---------------------------------------------------
__device__ __forceinline__ ull pack2(float lo, float hi){
    ull r; asm("mov.b64 %0, {%1,%2};" : "=l"(r) : "f"(lo), "f"(hi)); return r;
}
__device__ __forceinline__ void unpack2(ull v, float& lo, float& hi){
    asm("mov.b64 {%0,%1}, %2;" : "=f"(lo), "=f"(hi) : "l"(v));
}
__device__ __forceinline__ ull fma2(ull a, ull b, ull c){
    ull d; asm("fma.rn.f32x2 %0, %1, %2, %3;" : "=l"(d) : "l"(a), "l"(b), "l"(c)); return d;
}
__device__ __forceinline__ float eluf(float x){ return x > 0.f ? x : (__expf(x)-1.f); }
__device__ __forceinline__ ull elu2(ull v){
    float lo, hi; unpack2(v, lo, hi);
    return pack2(eluf(lo), eluf(hi));
}

// software grid barrier: all threads fence, t0 does ticket protocol
__device__ __forceinline__ void gridBar(int t){
    __syncthreads();
    __threadfence();
    if (t==0){
        unsigned my = *((volatile unsigned*)&g_bar_phase);
        unsigned old = atomicAdd(&g_bar_count, 1u);
        if (old == 127u){
            g_bar_count = 0;
            __threadfence();
            atomicExch(&g_bar_phase, my + 1u);
        } else {
            while (*((volatile unsigned*)&g_bar_phase) == my) { }
        }
        __threadfence();
    }
    __syncthreads();
}

// two-value reduction over 192 threads (6 warps)
__device__ __forceinline__ float2 blockRed2(float a, float b, float* sm, int t){
    #pragma unroll
    for (int o=16;o;o>>=1){
        a += __shfl_xor_sync(0xffffffffu, a, o);
        b += __shfl_xor_sync(0xffffffffu, b, o);
    }
    if ((t&31)==0){ sm[(t>>5)*2]=a; sm[(t>>5)*2+1]=b; }
    __syncthreads();
    float2 r;
    r.x = (sm[0]+sm[2])+(sm[4]+sm[6])+(sm[8]+sm[10]);
    r.y = (sm[1]+sm[3])+(sm[5]+sm[7])+(sm[9]+sm[11]);
    return r;
}

// ---------------------------------------------------------------------------
__global__ void zero_grid_kernel(){
    int i = blockIdx.x*blockDim.x + threadIdx.x;
    if (i < GRIDN) g_grid[i] = 0.f;
}

// ---------------- point stage ----------------------------------------------
__device__ __forceinline__ void disty_one(float px, float py, float pz,
                                          float f[12], int& cellpad)
{
    const float CLIPHI = 15.0f - 1e-4f;
    float cx = floorf(fminf(fmaxf(px,0.f), CLIPHI));
    float cy = floorf(fminf(fmaxf(py,0.f), CLIPHI));
    float cz = floorf(fminf(fmaxf(pz,0.f), CLIPHI));
    float ocx = px-(cx+0.5f), ocy = py-(cy+0.5f), ocz = pz-(cz+0.5f);
    float olx = px-cx,        oly = py-cy,        olz = pz-cz;
    float oux = px-(cx+1.f),  ouy = py-(cy+1.f),  ouz = pz-(cz+1.f);
    f[0]=ocx; f[1]=ocy; f[2]=ocz;
    f[3]=olx; f[4]=oly; f[5]=olz;
    f[6]=oux; f[7]=ouy; f[8]=ouz;
    f[9]  = sqrtf(ocx*ocx+ocy*ocy+ocz*ocz);
    f[10] = sqrtf(olx*olx+oly*oly+olz*olz);
    f[11] = sqrtf(oux*oux+ouy*ouy+ouz*ouz);
    cellpad = ((int)cx+2)*PLANE + ((int)cy+2)*24 + ((int)cz+2);
}

__global__ void __launch_bounds__(256,2)
point_kernel(const float* __restrict__ P0, const float* __restrict__ P1,
             const float* __restrict__ P2,
             const float* __restrict__ W1, const float* __restrict__ B1,
             const float* __restrict__ W2, const float* __restrict__ B2,
             const float* __restrict__ W3, const float* __restrict__ B3)
{
    __shared__ __align__(16) ull pW1[192], pW2[256], pW3[64];
    __shared__ ull pb1[16], pb2[16], pb3[4];
    int t = threadIdx.x;
    for (int i=t;i<192;i+=256) pW1[i]=pack2(W1[i],W1[i]);
    for (int i=t;i<256;i+=256) pW2[i]=pack2(W2[i],W2[i]);
    for (int i=t;i<64; i+=256) pW3[i]=pack2(W3[i],W3[i]);
    if (t<16){ pb1[t]=pack2(B1[t],B1[t]); pb2[t]=pack2(B2[t],B2[t]); }
    if (t<4)  pb3[t]=pack2(B3[t],B3[t]);
    __syncthreads();

    const float* pts = (blockIdx.y==0) ? P0 : (blockIdx.y==1 ? P1 : P2);
    int chan = blockIdx.y*4;

    long tid = (long)blockIdx.x*256 + t;
    long p0  = tid*2;
    if (p0 >= PPC) return;

    const float2* v = (const float2*)(pts + p0*3);
    float2 f0=v[0], f1=v[1], f2=v[2];
    float fa[12], fb[12]; int ca, cb;
    disty_one(f0.x, f0.y, f1.x, fa, ca);
    disty_one(f1.y, f2.x, f2.y, fb, cb);

    ull X[12];
    #pragma unroll
    for (int k=0;k<12;k++) X[k]=pack2(fa[k],fb[k]);

    ull H[16];
    #pragma unroll
    for (int j=0;j<16;j+=2){
        ull a0=pb1[j], a1=pb1[j+1];
        #pragma unroll
        for (int k=0;k<12;k++){
            ulonglong2 w = *(const ulonglong2*)&pW1[k*16+j];
            a0 = fma2(X[k], w.x, a0);
            a1 = fma2(X[k], w.y, a1);
        }
        H[j]   = elu2(a0);
        H[j+1] = elu2(a1);
    }

    ull H2[16];
    #pragma unroll
    for (int j=0;j<16;j+=2){
        ull a0=pb2[j], a1=pb2[j+1];
        #pragma unroll
        for (int k=0;k<16;k++){
            ulonglong2 w = *(const ulonglong2*)&pW2[k*16+j];
            a0 = fma2(H[k], w.x, a0);
            a1 = fma2(H[k], w.y, a1);
        }
        H2[j]   = elu2(a0);
        H2[j+1] = elu2(a1);
    }

    int b = (int)(p0 / NPTS);
    int baseA = b*BSTR + chan*CSTR + ca;
    int baseB = b*BSTR + chan*CSTR + cb;
    #pragma unroll
    for (int j=0;j<4;j++){
        ull a = pb3[j];
        #pragma unroll
        for (int k=0;k<16;k++) a = fma2(H2[k], pW3[k*4+j], a);
        float v0, v1; unpack2(a, v0, v1);
        if (v0 > 0.f) atomicMax((int*)&g_grid[baseA + j*CSTR], __float_as_int(v0));
        if (v1 > 0.f) atomicMax((int*)&g_grid[baseB + j*CSTR], __float_as_int(v1));
    }
}

// ---------------- fused conv stack ------------------------------------------
// grid 128 = (oc8, b4, odp4), 192 threads = (ic up-to-12, odl2, oh8).
// Each thread computes 8 ow outputs (register sliding) for ONE input channel;
// ic-partials reduced via smem -> FFMA-issue-bound instead of LDS-latency-bound.
__global__ void __launch_bounds__(192,1)
conv_stack_kernel(const float* __restrict__ w1,
                  const float* __restrict__ wS,
                  const float* __restrict__ bn1_g, const float* __restrict__ bn1_b,
                  const float* __restrict__ bns_g, const float* __restrict__ bns_b,
                  float* __restrict__ outp)
{
    __shared__ __align__(16) float sIn[6912];    // [8 ic][6 dd][12 h][12 w]
    __shared__ __align__(16) float wsm[1600];    // [8 ic][5 kd][5 kh][8 kw-pad]
    __shared__ __align__(16) float sAcc[1536];   // [<=12 ic][128 out]
    __shared__ float sSc[8], sSh[8], sred[12];

    int oc = blockIdx.x & 7, b = (blockIdx.x>>3) & 3, odp = blockIdx.x>>5;
    int t = threadIdx.x;
    int cic  = t>>4;          // 0..11
    int codl = (t>>3)&1;
    int coh  = t&7;
    int obase = b*4096 + oc*512 + odp*128;       // output base, +t (t<128)

    // ================= conv1: 12->8, k5, s2, p2, direct-from-L2 =============
    float accL;
    {
        float a[8] = {0.f,0.f,0.f,0.f,0.f,0.f,0.f,0.f};
        const float* gch = g_grid + (b*12+cic)*CSTR;
        const float* wp0 = w1 + (oc*12+cic)*125;
        int od = odp*2 + codl;
        #pragma unroll
        for (int kd=0;kd<5;kd++){
            #pragma unroll
            for (int kh=0;kh<5;kh++){
                const float* row = gch + (2*od+kd)*PLANE + (2*coh+kh)*24;
                float4 r0 = *(const float4*)(row);
                float4 r1 = *(const float4*)(row+4);
                float4 r2 = *(const float4*)(row+8);
                float4 r3 = *(const float4*)(row+12);
                float4 r4 = *(const float4*)(row+16);
                float rr[20] = {r0.x,r0.y,r0.z,r0.w, r1.x,r1.y,r1.z,r1.w,
                                r2.x,r2.y,r2.z,r2.w, r3.x,r3.y,r3.z,r3.w,
                                r4.x,r4.y,r4.z,r4.w};
                const float* wp = wp0 + kd*25 + kh*5;
                float wk0=__ldg(wp), wk1=__ldg(wp+1), wk2=__ldg(wp+2),
                      wk3=__ldg(wp+3), wk4=__ldg(wp+4);
                #pragma unroll
                for (int ow=0;ow<8;ow++){
                    a[ow] += rr[2*ow+0]*wk0;
                    a[ow] += rr[2*ow+1]*wk1;
                    a[ow] += rr[2*ow+2]*wk2;
                    a[ow] += rr[2*ow+3]*wk3;
                    a[ow] += rr[2*ow+4]*wk4;
                }
            }
        }
        int oidx = codl*64 + coh*8;
        #pragma unroll
        for (int ow=0;ow<8;ow++) sAcc[cic*128 + oidx + ow] = a[ow];
        __syncthreads();

        float s = 0.f;
        if (t < 128){
            #pragma unroll
            for (int ic=0;ic<12;ic++) s += sAcc[ic*128 + t];
            __stcg(&g_bufA[obase + t], s);
        }
        accL = s;
        float2 r = blockRed2(t<128 ? s : 0.f, t<128 ? s*s : 0.f, sred, t);
        if (t==0){ g_slots0[oc*16 + b*4 + odp] = r; }
    }
    gridBar(t);

    // ================= 6x (input BN+ELU -> conv 8->8 k5 p2) =================
    for (int L=0; L<6; L++){
        int dir = L & 1;
        const float*  rin  = dir ? g_bufB   : g_bufA;
        float*        rout = dir ? g_bufA   : g_bufB;
        const float2* sinp = dir ? g_slots1 : g_slots0;
        float2*       sout = dir ? g_slots0 : g_slots1;
        const float*  gin  = (L==0) ? bn1_g : (bns_g + (L-1)*8);
        const float*  bin  = (L==0) ? bn1_b : (bns_b + (L-1)*8);
        const float*  w    = wS + L*8000;

        __syncthreads();   // protect sAcc/sSc reuse
        if (t < 8){
            float sx=0.f, sy=0.f;
            #pragma unroll
            for (int q=0;q<16;q++){
                float2 p = *(const float2*)&sinp[t*16+q];
                sx+=p.x; sy+=p.y;
            }
            float m  = sx*(1.f/2048.f);
            float vr = sy*(1.f/2048.f) - m*m;
            float sc = gin[t]*rsqrtf(vr + 1e-5f);
            sSc[t]=sc; sSh[t]=bin[t]-m*sc;
        }
        float4 z4 = make_float4(0.f,0.f,0.f,0.f);
        for (int i=t;i<1728;i+=192) ((float4*)sIn)[i] = z4;
        for (int i=t;i<1000;i+=192){
            int ic=i/125, r=i%125, kd=r/25, kh=(r%25)/5, kw=r%5;
            wsm[((ic*5+kd)*5+kh)*8 + kw] = w[oc*1000 + i];
        }
        __syncthreads();

        for (int i=t;i<768;i+=192){
            int half = i&1, h = (i>>1)&7, dd = (i>>4)%6, ic = i/96;
            int id = odp*2 - 2 + dd;
            if ((unsigned)id < 8u){
                float4 v = __ldcg((const float4*)(rin + b*4096 + ic*512 + id*64 + h*8 + half*4));
                float sc = sSc[ic], sh = sSh[ic];
                float* d = sIn + ic*864 + dd*144 + (h+2)*12 + 2 + half*4;
                d[0]=eluf(v.x*sc+sh); d[1]=eluf(v.y*sc+sh);
                d[2]=eluf(v.z*sc+sh); d[3]=eluf(v.w*sc+sh);
            }
        }
        __syncthreads();

        float a[8] = {0.f,0.f,0.f,0.f,0.f,0.f,0.f,0.f};
        if (t < 128){   // cic 0..7
            const float* cb = sIn + cic*864;
            const float* wb = wsm + cic*200;
            #pragma unroll
            for (int kd=0;kd<5;kd++){
                #pragma unroll
                for (int kh=0;kh<5;kh++){
                    const float* row = cb + (codl+kd)*144 + (coh+kh)*12;
                    float4 r0 = *(const float4*)(row);
                    float4 r1 = *(const float4*)(row+4);
                    float4 r2 = *(const float4*)(row+8);
                    float rr[12] = {r0.x,r0.y,r0.z,r0.w, r1.x,r1.y,r1.z,r1.w,
                                    r2.x,r2.y,r2.z,r2.w};
                    const float* wp = wb + (kd*5+kh)*8;
                    float4 wv = *(const float4*)wp;
                    float wk4 = wp[4];
                    #pragma unroll
                    for (int ow=0;ow<8;ow++){
                        a[ow] += rr[ow+0]*wv.x;
                        a[ow] += rr[ow+1]*wv.y;
                        a[ow] += rr[ow+2]*wv.z;
                        a[ow] += rr[ow+3]*wv.w;
                        a[ow] += rr[ow+4]*wk4;
                    }
                }
            }
            int oidx = codl*64 + coh*8;
            #pragma unroll
            for (int ow=0;ow<8;ow++) sAcc[cic*128 + oidx + ow] = a[ow];
        }
        __syncthreads();

        float s = 0.f;
        if (t < 128){
            #pragma unroll
            for (int ic=0;ic<8;ic++) s += sAcc[ic*128 + t];
            __stcg(&rout[obase + t], s);
        }
        accL = s;
        float2 r = blockRed2(t<128 ? s : 0.f, t<128 ? s*s : 0.f, sred, t);
        if (t==0){ sout[oc*16 + b*4 + odp] = r; }
        gridBar(t);
    }

    // ================= final BN+ELU from live accumulator ===================
    if (t < 128){
        float sx=0.f, sy=0.f;
        #pragma unroll
        for (int q=0;q<16;q++){
            float2 p = *(const float2*)&g_slots0[oc*16+q];
            sx+=p.x; sy+=p.y;
        }
        float m  = sx*(1.f/2048.f);
        float vr = sy*(1.f/2048.f) - m*m;
        float sc = bns_g[40+oc]*rsqrtf(vr + 1e-5f);
        float sh = bns_b[40+oc]-m*sc;
        outp[(b*8+oc)*512 + odp*128 + t] = eluf(accL*sc+sh);
    }
}

// ---------------------------------------------------------------------------
extern "C" void kernel_launch(void* const* d_in, const int* in_sizes, int n_in,
                              void* d_out, int out_size)
{
    const float* goals       = (const float*)d_in[0];
    const float* inputs      = (const float*)d_in[1];
    const float* backgrounds = (const float*)d_in[2];
    const float* W1 = (const float*)d_in[3];
    const float* b1 = (const float*)d_in[4];
    const float* W2 = (const float*)d_in[5];
    const float* b2 = (const float*)d_in[6];
    const float* W3 = (const float*)d_in[7];
    const float* b3 = (const float*)d_in[8];
    const float* conv1_w = (const float*)d_in[9];
    const float* bn1_g   = (const float*)d_in[11];
    const float* bn1_b   = (const float*)d_in[12];
    const float* convs_w = (const float*)d_in[13];
    const float* bns_g   = (const float*)d_in[15];
    const float* bns_b   = (const float*)d_in[16];
    float* out = (float*)d_out;

    zero_grid_kernel<<<(GRIDN+255)/256, 256>>>();

    dim3 pg((PPC/2 + 255)/256, 3);
    point_kernel<<<pg,256>>>(inputs, goals, backgrounds, W1,b1,W2,b2,W3,b3);

    conv_stack_kernel<<<128,192>>>(conv1_w, convs_w, bn1_g, bn1_b,
                                   bns_g, bns_b, out);
}

// round 9
// speedup vs baseline: 1.5159x; 1.0887x over previous
#include <cuda_runtime.h>
#include <math.h>

#define G     15
#define NB    4
#define NPTS  300000
#define PPC   (NB*NPTS)

// padded grid: [B][12][19 planes][19 rows][24 cols]; aligned rows
#define PLANE 456
#define CSTR  8672
#define BSTR  (12*CSTR)
#define GRIDN (NB*BSTR)

typedef unsigned long long ull;

__device__ float  g_grid[GRIDN];
__device__ float  g_bufA[NB*8*512];
__device__ float  g_bufB[NB*8*512];
__device__ float2 g_slots0[128];
__device__ float2 g_slots1[128];
__device__ unsigned g_flags[128];
__device__ unsigned g_phasev = 0;

// ---------------- helpers ---------------------------------------------------
__device__ __forceinline__ ull pack2(float lo, float hi){
    ull r; asm("mov.b64 %0, {%1,%2};" : "=l"(r) : "f"(lo), "f"(hi)); return r;
}
__device__ __forceinline__ void unpack2(ull v, float& lo, float& hi){
    asm("mov.b64 {%0,%1}, %2;" : "=f"(lo), "=f"(hi) : "l"(v));
}
__device__ __forceinline__ ull fma2(ull a, ull b, ull c){
    ull d; asm("fma.rn.f32x2 %0, %1, %2, %3;" : "=l"(d) : "l"(a), "l"(b), "l"(c)); return d;
}
__device__ __forceinline__ float eluf(float x){ return x > 0.f ? x : (__expf(x)-1.f); }
__device__ __forceinline__ ull elu2(ull v){
    float lo, hi; unpack2(v, lo, hi);
    return pack2(eluf(lo), eluf(hi));
}

// flag-based grid barrier: per-block flag stores, block0 detects in parallel,
// releases via phase word. Monotonic across graph replays.
__device__ __forceinline__ void gridBar(int t, int bid){
    __shared__ unsigned sMy;
    __syncthreads();
    __threadfence();
    if (t==0) sMy = *((volatile unsigned*)&g_phasev);
    __syncthreads();
    unsigned nxt = sMy + 1u;
    if (bid == 0){
        if (t < 127){
            while (((volatile unsigned*)g_flags)[t+1] != nxt) { }
        }
        __syncthreads();
        __threadfence();
        if (t==0) *((volatile unsigned*)&g_phasev) = nxt;
    } else {
        if (t==0){
            ((volatile unsigned*)g_flags)[bid] = nxt;
            while (*((volatile unsigned*)&g_phasev) != nxt) { }
        }
    }
    __syncthreads();
    __threadfence();
}

// two-value reduction over 192 threads (6 warps)
__device__ __forceinline__ float2 blockRed2(float a, float b, float* sm, int t){
    #pragma unroll
    for (int o=16;o;o>>=1){
        a += __shfl_xor_sync(0xffffffffu, a, o);
        b += __shfl_xor_sync(0xffffffffu, b, o);
    }
    if ((t&31)==0){ sm[(t>>5)*2]=a; sm[(t>>5)*2+1]=b; }
    __syncthreads();
    float2 r;
    r.x = (sm[0]+sm[2])+(sm[4]+sm[6])+(sm[8]+sm[10]);
    r.y = (sm[1]+sm[3])+(sm[5]+sm[7])+(sm[9]+sm[11]);
    return r;
}

// ---------------- point stage ----------------------------------------------
// Layer-1 algebra: off_l = oc+0.5, off_u = oc-0.5  =>  6 effective inputs:
// {oc x,y,z} with folded weights, {n_c,n_l,n_u}, and an effective bias.
__device__ __forceinline__ void disty6(float px, float py, float pz,
                                       float f[6], int& cellpad)
{
    const float CLIPHI = 15.0f - 1e-4f;
    float cx = floorf(fminf(fmaxf(px,0.f), CLIPHI));
    float cy = floorf(fminf(fmaxf(py,0.f), CLIPHI));
    float cz = floorf(fminf(fmaxf(pz,0.f), CLIPHI));
    float ocx = px-cx-0.5f, ocy = py-cy-0.5f, ocz = pz-cz-0.5f;
    float lx = ocx+0.5f, ly = ocy+0.5f, lz = ocz+0.5f;
    float ux = ocx-0.5f, uy = ocy-0.5f, uz = ocz-0.5f;
    f[0]=ocx; f[1]=ocy; f[2]=ocz;
    f[3] = sqrtf(ocx*ocx+ocy*ocy+ocz*ocz);
    f[4] = sqrtf(lx*lx+ly*ly+lz*lz);
    f[5] = sqrtf(ux*ux+uy*uy+uz*uz);
    cellpad = ((int)cx+2)*PLANE + ((int)cy+2)*24 + ((int)cz+2);
}

__global__ void __launch_bounds__(256,2)
point_kernel(const float* __restrict__ P0, const float* __restrict__ P1,
             const float* __restrict__ P2,
             const float* __restrict__ W1, const float* __restrict__ B1,
             const float* __restrict__ W2, const float* __restrict__ B2,
             const float* __restrict__ W3, const float* __restrict__ B3)
{
    __shared__ __align__(16) ull pW1e[96], pW2[256], pW3[64];
    __shared__ ull pb1e[16], pb2[16], pb3[4];
    int t = threadIdx.x;
    for (int i=t;i<256;i+=256) pW2[i]=pack2(W2[i],W2[i]);
    for (int i=t;i<64; i+=256) pW3[i]=pack2(W3[i],W3[i]);
    if (t<16){
        // effective L1 weights/bias for 6-input form
        float a0 = W1[0*16+t]+W1[3*16+t]+W1[6*16+t];
        float a1 = W1[1*16+t]+W1[4*16+t]+W1[7*16+t];
        float a2 = W1[2*16+t]+W1[5*16+t]+W1[8*16+t];
        pW1e[0*16+t]=pack2(a0,a0);
        pW1e[1*16+t]=pack2(a1,a1);
        pW1e[2*16+t]=pack2(a2,a2);
        float n0=W1[9*16+t], n1=W1[10*16+t], n2=W1[11*16+t];
        pW1e[3*16+t]=pack2(n0,n0);
        pW1e[4*16+t]=pack2(n1,n1);
        pW1e[5*16+t]=pack2(n2,n2);
        float be = B1[t] + 0.5f*((W1[3*16+t]+W1[4*16+t]+W1[5*16+t])
                               - (W1[6*16+t]+W1[7*16+t]+W1[8*16+t]));
        pb1e[t]=pack2(be,be);
        pb2[t]=pack2(B2[t],B2[t]);
    }
    if (t<4) pb3[t]=pack2(B3[t],B3[t]);
    __syncthreads();

    const float* pts = (blockIdx.y==0) ? P0 : (blockIdx.y==1 ? P1 : P2);
    int chan = blockIdx.y*4;

    long tid = (long)blockIdx.x*256 + t;
    long p0  = tid*2;
    if (p0 >= PPC) return;

    const float2* v = (const float2*)(pts + p0*3);
    float2 f0=v[0], f1=v[1], f2=v[2];
    float fa[6], fb[6]; int ca, cb;
    disty6(f0.x, f0.y, f1.x, fa, ca);
    disty6(f1.y, f2.x, f2.y, fb, cb);

    ull X[6];
    #pragma unroll
    for (int k=0;k<6;k++) X[k]=pack2(fa[k],fb[k]);

    ull H[16];
    #pragma unroll
    for (int j=0;j<16;j+=2){
        ull a0=pb1e[j], a1=pb1e[j+1];
        #pragma unroll
        for (int k=0;k<6;k++){
            ulonglong2 w = *(const ulonglong2*)&pW1e[k*16+j];
            a0 = fma2(X[k], w.x, a0);
            a1 = fma2(X[k], w.y, a1);
        }
        H[j]   = elu2(a0);
        H[j+1] = elu2(a1);
    }

    ull H2[16];
    #pragma unroll
    for (int j=0;j<16;j+=2){
        ull a0=pb2[j], a1=pb2[j+1];
        #pragma unroll
        for (int k=0;k<16;k++){
            ulonglong2 w = *(const ulonglong2*)&pW2[k*16+j];
            a0 = fma2(H[k], w.x, a0);
            a1 = fma2(H[k], w.y, a1);
        }
        H2[j]   = elu2(a0);
        H2[j+1] = elu2(a1);
    }

    int b = (int)(p0 / NPTS);
    int baseA = b*BSTR + chan*CSTR + ca;
    int baseB = b*BSTR + chan*CSTR + cb;
    #pragma unroll
    for (int j=0;j<4;j++){
        ull a = pb3[j];
        #pragma unroll
        for (int k=0;k<16;k++) a = fma2(H2[k], pW3[k*4+j], a);
        float v0, v1; unpack2(a, v0, v1);
        if (v0 > 0.f) atomicMax((int*)&g_grid[baseA + j*CSTR], __float_as_int(v0));
        if (v1 > 0.f) atomicMax((int*)&g_grid[baseB + j*CSTR], __float_as_int(v1));
    }
}

// ---------------- fused conv stack ------------------------------------------
// grid 128 = (oc8, b4, odp4), 192 threads = (ic, odl2, oh8)
__global__ void __launch_bounds__(192,1)
conv_stack_kernel(const float* __restrict__ w1,
                  const float* __restrict__ wS,
                  const float* __restrict__ bn1_g, const float* __restrict__ bn1_b,
                  const float* __restrict__ bns_g, const float* __restrict__ bns_b,
                  float* __restrict__ outp)
{
    __shared__ __align__(16) float sIn[6912];    // [8 ic][6 dd][12 h][12 w]
    __shared__ __align__(16) float wsm[1600];    // [8 ic][5 kd][5 kh][8 kw-pad]
    __shared__ __align__(16) float sAcc[1536];   // [<=12 ic][128 out]
    __shared__ float sSc[8], sSh[8], sred[12];

    int bid = blockIdx.x;
    int oc = bid & 7, b = (bid>>3) & 3, odp = bid>>5;
    int t = threadIdx.x;
    int cic  = t>>4;
    int codl = (t>>3)&1;
    int coh  = t&7;
    int obase = b*4096 + oc*512 + odp*128;

    // zero sIn once; out-of-range halo cells are identical every layer
    {
        float4 z4 = make_float4(0.f,0.f,0.f,0.f);
        for (int i=t;i<1728;i+=192) ((float4*)sIn)[i] = z4;
    }

    // ================= conv1: 12->8, k5, s2, p2, direct-from-L2 =============
    float accL;
    {
        float a[8] = {0.f,0.f,0.f,0.f,0.f,0.f,0.f,0.f};
        const float* gch = g_grid + (b*12+cic)*CSTR;
        const float* wp0 = w1 + (oc*12+cic)*125;
        int od = odp*2 + codl;
        #pragma unroll
        for (int kd=0;kd<5;kd++){
            #pragma unroll
            for (int kh=0;kh<5;kh++){
                const float* row = gch + (2*od+kd)*PLANE + (2*coh+kh)*24;
                float4 r0 = *(const float4*)(row);
                float4 r1 = *(const float4*)(row+4);
                float4 r2 = *(const float4*)(row+8);
                float4 r3 = *(const float4*)(row+12);
                float4 r4 = *(const float4*)(row+16);
                float rr[20] = {r0.x,r0.y,r0.z,r0.w, r1.x,r1.y,r1.z,r1.w,
                                r2.x,r2.y,r2.z,r2.w, r3.x,r3.y,r3.z,r3.w,
                                r4.x,r4.y,r4.z,r4.w};
                const float* wp = wp0 + kd*25 + kh*5;
                float wk0=__ldg(wp), wk1=__ldg(wp+1), wk2=__ldg(wp+2),
                      wk3=__ldg(wp+3), wk4=__ldg(wp+4);
                #pragma unroll
                for (int ow=0;ow<8;ow++){
                    a[ow] += rr[2*ow+0]*wk0;
                    a[ow] += rr[2*ow+1]*wk1;
                    a[ow] += rr[2*ow+2]*wk2;
                    a[ow] += rr[2*ow+3]*wk3;
                    a[ow] += rr[2*ow+4]*wk4;
                }
            }
        }
        int oidx = codl*64 + coh*8;
        #pragma unroll
        for (int ow=0;ow<8;ow++) sAcc[cic*128 + oidx + ow] = a[ow];
        __syncthreads();

        float s = 0.f;
        if (t < 128){
            #pragma unroll
            for (int ic=0;ic<12;ic++) s += sAcc[ic*128 + t];
            __stcg(&g_bufA[obase + t], s);
        }
        accL = s;
        float2 r = blockRed2(t<128 ? s : 0.f, t<128 ? s*s : 0.f, sred, t);
        if (t==0){ g_slots0[oc*16 + b*4 + odp] = r; }
    }
    gridBar(t, bid);

    // ================= 6x (input BN+ELU -> conv 8->8 k5 p2) =================
    for (int L=0; L<6; L++){
        int dir = L & 1;
        const float*  rin  = dir ? g_bufB   : g_bufA;
        float*        rout = dir ? g_bufA   : g_bufB;
        const float2* sinp = dir ? g_slots1 : g_slots0;
        float2*       sout = dir ? g_slots0 : g_slots1;
        const float*  gin  = (L==0) ? bn1_g : (bns_g + (L-1)*8);
        const float*  bin  = (L==0) ? bn1_b : (bns_b + (L-1)*8);
        const float*  w    = wS + L*8000;

        if (t < 8){
            float sx=0.f, sy=0.f;
            #pragma unroll
            for (int q=0;q<16;q++){
                float2 p = *(const float2*)&sinp[t*16+q];
                sx+=p.x; sy+=p.y;
            }
            float m  = sx*(1.f/2048.f);
            float vr = sy*(1.f/2048.f) - m*m;
            float sc = gin[t]*rsqrtf(vr + 1e-5f);
            sSc[t]=sc; sSh[t]=bin[t]-m*sc;
        }
        for (int i=t;i<1000;i+=192){
            int ic=i/125, r=i%125, kd=r/25, kh=(r%25)/5, kw=r%5;
            wsm[((ic*5+kd)*5+kh)*8 + kw] = w[oc*1000 + i];
        }
        __syncthreads();

        // batched interior fill: 4 predicated ldcg first, then ELU+store
        {
            float4 vv[4]; bool ok[4]; int di[4];
            #pragma unroll
            for (int u=0;u<4;u++){
                int i = t + u*192;
                int half = i&1, h = (i>>1)&7, dd = (i>>4)%6, ic = i/96;
                int id = odp*2 - 2 + dd;
                ok[u] = (unsigned)id < 8u;
                di[u] = ic*864 + dd*144 + (h+2)*12 + 2 + half*4;
                if (ok[u])
                    vv[u] = __ldcg((const float4*)(rin + b*4096 + ic*512 + id*64 + h*8 + half*4));
            }
            #pragma unroll
            for (int u=0;u<4;u++){
                if (ok[u]){
                    int i = t + u*192;
                    int ic = i/96;
                    float sc = sSc[ic], sh = sSh[ic];
                    float* d = sIn + di[u];
                    d[0]=eluf(vv[u].x*sc+sh); d[1]=eluf(vv[u].y*sc+sh);
                    d[2]=eluf(vv[u].z*sc+sh); d[3]=eluf(vv[u].w*sc+sh);
                }
            }
        }
        __syncthreads();

        float a[8] = {0.f,0.f,0.f,0.f,0.f,0.f,0.f,0.f};
        if (t < 128){
            const float* cb = sIn + cic*864;
            const float* wb = wsm + cic*200;
            #pragma unroll
            for (int kd=0;kd<5;kd++){
                #pragma unroll
                for (int kh=0;kh<5;kh++){
                    const float* row = cb + (codl+kd)*144 + (coh+kh)*12;
                    float4 r0 = *(const float4*)(row);
                    float4 r1 = *(const float4*)(row+4);
                    float4 r2 = *(const float4*)(row+8);
                    float rr[12] = {r0.x,r0.y,r0.z,r0.w, r1.x,r1.y,r1.z,r1.w,
                                    r2.x,r2.y,r2.z,r2.w};
                    const float* wp = wb + (kd*5+kh)*8;
                    float4 wv = *(const float4*)wp;
                    float wk4 = wp[4];
                    #pragma unroll
                    for (int ow=0;ow<8;ow++){
                        a[ow] += rr[ow+0]*wv.x;
                        a[ow] += rr[ow+1]*wv.y;
                        a[ow] += rr[ow+2]*wv.z;
                        a[ow] += rr[ow+3]*wv.w;
                        a[ow] += rr[ow+4]*wk4;
                    }
                }
            }
            int oidx = codl*64 + coh*8;
            #pragma unroll
            for (int ow=0;ow<8;ow++) sAcc[cic*128 + oidx + ow] = a[ow];
        }
        __syncthreads();

        float s = 0.f;
        if (t < 128){
            #pragma unroll
            for (int ic=0;ic<8;ic++) s += sAcc[ic*128 + t];
            __stcg(&rout[obase + t], s);
        }
        accL = s;
        float2 r = blockRed2(t<128 ? s : 0.f, t<128 ? s*s : 0.f, sred, t);
        if (t==0){ sout[oc*16 + b*4 + odp] = r; }
        gridBar(t, bid);
    }

    // ================= final BN+ELU from live accumulator ===================
    if (t < 128){
        float sx=0.f, sy=0.f;
        #pragma unroll
        for (int q=0;q<16;q++){
            float2 p = *(const float2*)&g_slots0[oc*16+q];
            sx+=p.x; sy+=p.y;
        }
        float m  = sx*(1.f/2048.f);
        float vr = sy*(1.f/2048.f) - m*m;
        float sc = bns_g[40+oc]*rsqrtf(vr + 1e-5f);
        float sh = bns_b[40+oc]-m*sc;
        outp[(b*8+oc)*512 + odp*128 + t] = eluf(accL*sc+sh);
    }
}

// ---------------------------------------------------------------------------
extern "C" void kernel_launch(void* const* d_in, const int* in_sizes, int n_in,
                              void* d_out, int out_size)
{
    const float* goals       = (const float*)d_in[0];
    const float* inputs      = (const float*)d_in[1];
    const float* backgrounds = (const float*)d_in[2];
    const float* W1 = (const float*)d_in[3];
    const float* b1 = (const float*)d_in[4];
    const float* W2 = (const float*)d_in[5];
    const float* b2 = (const float*)d_in[6];
    const float* W3 = (const float*)d_in[7];
    const float* b3 = (const float*)d_in[8];
    const float* conv1_w = (const float*)d_in[9];
    const float* bn1_g   = (const float*)d_in[11];
    const float* bn1_b   = (const float*)d_in[12];
    const float* convs_w = (const float*)d_in[13];
    const float* bns_g   = (const float*)d_in[15];
    const float* bns_b   = (const float*)d_in[16];
    float* out = (float*)d_out;

    void* gptr = nullptr;
    cudaGetSymbolAddress(&gptr, g_grid);
    cudaMemsetAsync(gptr, 0, GRIDN*sizeof(float));

    dim3 pg((PPC/2 + 255)/256, 3);
    point_kernel<<<pg,256>>>(inputs, goals, backgrounds, W1,b1,W2,b2,W3,b3);

    conv_stack_kernel<<<128,192>>>(conv1_w, convs_w, bn1_g, bn1_b,
                                   bns_g, bns_b, out);
}

// round 10
// speedup vs baseline: 1.6075x; 1.0604x over previous
#include <cuda_runtime.h>
#include <math.h>

#define G     15
#define NB    4
#define NPTS  300000
#define PPC   (NB*NPTS)

// padded grid: [B][12][19 planes][19 rows][24 cols]
#define PLANE 456
#define CSTR  8672
#define BSTR  (12*CSTR)
#define GRIDN (NB*BSTR)

typedef unsigned long long ull;

__device__ float  g_grid[GRIDN];
__device__ float  g_bufA[NB*8*512];
__device__ float  g_bufB[NB*8*512];
__device__ float2 g_slots0[128];
__device__ float2 g_slots1[128];
__device__ unsigned g_flags[128];
__device__ unsigned g_phasev = 0;

// ---------------- helpers ---------------------------------------------------
__device__ __forceinline__ ull pack2(float lo, float hi){
    ull r; asm("mov.b64 %0, {%1,%2};" : "=l"(r) : "f"(lo), "f"(hi)); return r;
}
__device__ __forceinline__ void unpack2(ull v, float& lo, float& hi){
    asm("mov.b64 {%0,%1}, %2;" : "=f"(lo), "=f"(hi) : "l"(v));
}
__device__ __forceinline__ ull fma2(ull a, ull b, ull c){
    ull d; asm("fma.rn.f32x2 %0, %1, %2, %3;" : "=l"(d) : "l"(a), "l"(b), "l"(c)); return d;
}
__device__ __forceinline__ float eluf(float x){ return x > 0.f ? x : (__expf(x)-1.f); }
__device__ __forceinline__ ull elu2(ull v){
    float lo, hi; unpack2(v, lo, hi);
    return pack2(eluf(lo), eluf(hi));
}

// flag-based grid barrier (block0 parallel detect + phase release; monotonic)
__device__ __forceinline__ void gridBar(int t, int bid){
    __shared__ unsigned sMy;
    __syncthreads();
    __threadfence();
    if (t==0) sMy = *((volatile unsigned*)&g_phasev);
    __syncthreads();
    unsigned nxt = sMy + 1u;
    if (bid == 0){
        if (t < 127){
            while (((volatile unsigned*)g_flags)[t+1] != nxt) { }
        }
        __syncthreads();
        __threadfence();
        if (t==0) *((volatile unsigned*)&g_phasev) = nxt;
    } else {
        if (t==0){
            ((volatile unsigned*)g_flags)[bid] = nxt;
            while (*((volatile unsigned*)&g_phasev) != nxt) { }
        }
    }
    __syncthreads();
    __threadfence();
}

// two-value reduction over 384 threads (12 warps)
__device__ __forceinline__ float2 blockRed2(float a, float b, float* sm, int t){
    #pragma unroll
    for (int o=16;o;o>>=1){
        a += __shfl_xor_sync(0xffffffffu, a, o);
        b += __shfl_xor_sync(0xffffffffu, b, o);
    }
    if ((t&31)==0){ sm[(t>>5)*2]=a; sm[(t>>5)*2+1]=b; }
    __syncthreads();
    float2 r; r.x=0.f; r.y=0.f;
    #pragma unroll
    for (int wq=0;wq<12;wq++){ r.x += sm[wq*2]; r.y += sm[wq*2+1]; }
    return r;
}

// ---------------- point stage: 1 pt/thread, channel-pair packed f32x2 -------
__device__ __forceinline__ void disty6(float px, float py, float pz,
                                       float f[6], int& cellpad)
{
    const float CLIPHI = 15.0f - 1e-4f;
    float cx = floorf(fminf(fmaxf(px,0.f), CLIPHI));
    float cy = floorf(fminf(fmaxf(py,0.f), CLIPHI));
    float cz = floorf(fminf(fmaxf(pz,0.f), CLIPHI));
    float ocx = px-cx-0.5f, ocy = py-cy-0.5f, ocz = pz-cz-0.5f;
    float lx = ocx+0.5f, ly = ocy+0.5f, lz = ocz+0.5f;
    float ux = ocx-0.5f, uy = ocy-0.5f, uz = ocz-0.5f;
    f[0]=ocx; f[1]=ocy; f[2]=ocz;
    f[3] = sqrtf(ocx*ocx+ocy*ocy+ocz*ocz);
    f[4] = sqrtf(lx*lx+ly*ly+lz*lz);
    f[5] = sqrtf(ux*ux+uy*uy+uz*uz);
    cellpad = ((int)cx+2)*PLANE + ((int)cy+2)*24 + ((int)cz+2);
}

__global__ void __launch_bounds__(256,3)
point_kernel(const float* __restrict__ P0, const float* __restrict__ P1,
             const float* __restrict__ P2,
             const float* __restrict__ W1, const float* __restrict__ B1,
             const float* __restrict__ W2, const float* __restrict__ B2,
             const float* __restrict__ W3, const float* __restrict__ B3)
{
    // channel-pair packed weights: pW1[k][jp] = {w[k][2jp], w[k][2jp+1]}
    __shared__ __align__(16) ull pW1[48], pW2[128], pW3[32];
    __shared__ ull pb1[8], pb2[8], pb3[2];
    int t = threadIdx.x;

    if (t < 48){
        int k = t>>3, jp = t&7, j0 = 2*jp, j1 = 2*jp+1;
        float w0, w1v;
        if (k < 3){
            w0  = W1[k*16+j0]+W1[(k+3)*16+j0]+W1[(k+6)*16+j0];
            w1v = W1[k*16+j1]+W1[(k+3)*16+j1]+W1[(k+6)*16+j1];
        } else {
            w0  = W1[(k+6)*16+j0];   // rows 9,10,11
            w1v = W1[(k+6)*16+j1];
        }
        pW1[k*8+jp] = pack2(w0, w1v);
    }
    if (t < 8){
        int j0 = 2*t, j1 = 2*t+1;
        float be0 = B1[j0] + 0.5f*((W1[3*16+j0]+W1[4*16+j0]+W1[5*16+j0])
                                 - (W1[6*16+j0]+W1[7*16+j0]+W1[8*16+j0]));
        float be1 = B1[j1] + 0.5f*((W1[3*16+j1]+W1[4*16+j1]+W1[5*16+j1])
                                 - (W1[6*16+j1]+W1[7*16+j1]+W1[8*16+j1]));
        pb1[t] = pack2(be0, be1);
        pb2[t] = pack2(B2[j0], B2[j1]);
    }
    if (t < 128){
        int k = t>>3, jp = t&7;
        pW2[k*8+jp] = pack2(W2[k*16+2*jp], W2[k*16+2*jp+1]);
    }
    if (t < 32){
        int k = t>>1, jp = t&1;
        pW3[k*2+jp] = pack2(W3[k*4+2*jp], W3[k*4+2*jp+1]);
    }
    if (t < 2) pb3[t] = pack2(B3[2*t], B3[2*t+1]);
    __syncthreads();

    const float* pts = (blockIdx.y==0) ? P0 : (blockIdx.y==1 ? P1 : P2);
    int chan = blockIdx.y*4;

    long pid = (long)blockIdx.x*256 + t;
    if (pid >= PPC) return;

    float px = pts[pid*3], py = pts[pid*3+1], pz = pts[pid*3+2];
    float fa[6]; int cell;
    disty6(px, py, pz, fa, cell);

    // layer 1: 6 eff inputs -> 16 (8 pairs), ELU
    ull h[8];
    {
        ull xx0=pack2(fa[0],fa[0]), xx1=pack2(fa[1],fa[1]), xx2=pack2(fa[2],fa[2]);
        ull xx3=pack2(fa[3],fa[3]), xx4=pack2(fa[4],fa[4]), xx5=pack2(fa[5],fa[5]);
        #pragma unroll
        for (int jp=0;jp<8;jp++){
            ull a = pb1[jp];
            a = fma2(xx0, pW1[0*8+jp], a);
            a = fma2(xx1, pW1[1*8+jp], a);
            a = fma2(xx2, pW1[2*8+jp], a);
            a = fma2(xx3, pW1[3*8+jp], a);
            a = fma2(xx4, pW1[4*8+jp], a);
            a = fma2(xx5, pW1[5*8+jp], a);
            h[jp] = elu2(a);
        }
    }

    // broadcast-pack h -> 16 {v,v}
    ull hh[16];
    #pragma unroll
    for (int jp=0;jp<8;jp++){
        float s0, s1; unpack2(h[jp], s0, s1);
        hh[2*jp]   = pack2(s0, s0);
        hh[2*jp+1] = pack2(s1, s1);
    }

    // layer 2: 16 -> 16 (8 pairs), ELU
    ull g[8];
    #pragma unroll
    for (int jp=0;jp<8;jp++){
        ull a = pb2[jp];
        #pragma unroll
        for (int k=0;k<16;k++) a = fma2(hh[k], pW2[k*8+jp], a);
        g[jp] = elu2(a);
    }
    #pragma unroll
    for (int jp=0;jp<8;jp++){
        float s0, s1; unpack2(g[jp], s0, s1);
        hh[2*jp]   = pack2(s0, s0);
        hh[2*jp+1] = pack2(s1, s1);
    }

    // layer 3: 16 -> 4 (2 pairs) + scatter-max
    int b = (int)(pid / NPTS);
    int base = b*BSTR + chan*CSTR + cell;
    #pragma unroll
    for (int jp=0;jp<2;jp++){
        ull a = pb3[jp];
        #pragma unroll
        for (int k=0;k<16;k++) a = fma2(hh[k], pW3[k*2+jp], a);
        float v0, v1; unpack2(a, v0, v1);
        if (v0 > 0.f) atomicMax((int*)&g_grid[base + (2*jp  )*CSTR], __float_as_int(v0));
        if (v1 > 0.f) atomicMax((int*)&g_grid[base + (2*jp+1)*CSTR], __float_as_int(v1));
    }
}

// ---------------- fused conv stack: 384 threads/block -----------------------
// grid 128 = (oc8, b4, odp4); thread = (cic, odl, oh, owh) computes 4 ow.
__global__ void __launch_bounds__(384,1)
conv_stack_kernel(const float* __restrict__ w1,
                  const float* __restrict__ wS,
                  const float* __restrict__ bn1_g, const float* __restrict__ bn1_b,
                  const float* __restrict__ bns_g, const float* __restrict__ bns_b,
                  float* __restrict__ outp)
{
    __shared__ __align__(16) float sIn[6912];    // [8 ic][6 dd][12 h][12 w]
    __shared__ __align__(16) float wsm[1600];    // [8 ic][5 kd][5 kh][8 kw-pad]
    __shared__ __align__(16) float sAcc[1536];   // [<=12 ic][128 out]
    __shared__ float sSc[8], sSh[8], sred[24];

    int bid = blockIdx.x;
    int oc = bid & 7, b = (bid>>3) & 3, odp = bid>>5;
    int t = threadIdx.x;
    int owh  = t&1;           // ow half: 0 -> ow 0..3, 1 -> ow 4..7
    int coh  = (t>>1)&7;
    int codl = (t>>4)&1;
    int cic  = t>>5;          // 0..11
    int obase = b*4096 + oc*512 + odp*128;

    { // zero sIn once (halo cells identical every layer)
        float4 z4 = make_float4(0.f,0.f,0.f,0.f);
        for (int i=t;i<1728;i+=384) ((float4*)sIn)[i] = z4;
    }

    // ================= conv1: 12->8, k5, s2, p2, direct-from-L2 =============
    float accL;
    {
        float a[4] = {0.f,0.f,0.f,0.f};
        const float* gch = g_grid + (b*12+cic)*CSTR;
        const float* wp0 = w1 + (oc*12+cic)*125;
        int od = odp*2 + codl;
        #pragma unroll
        for (int kd=0;kd<5;kd++){
            #pragma unroll
            for (int kh=0;kh<5;kh++){
                const float* row = gch + (2*od+kd)*PLANE + (2*coh+kh)*24 + 8*owh;
                float4 r0 = *(const float4*)(row);
                float4 r1 = *(const float4*)(row+4);
                float4 r2 = *(const float4*)(row+8);
                float rr[12] = {r0.x,r0.y,r0.z,r0.w, r1.x,r1.y,r1.z,r1.w,
                                r2.x,r2.y,r2.z,r2.w};
                const float* wp = wp0 + kd*25 + kh*5;
                float wk0=__ldg(wp), wk1=__ldg(wp+1), wk2=__ldg(wp+2),
                      wk3=__ldg(wp+3), wk4=__ldg(wp+4);
                #pragma unroll
                for (int o=0;o<4;o++){
                    a[o] += rr[2*o+0]*wk0;
                    a[o] += rr[2*o+1]*wk1;
                    a[o] += rr[2*o+2]*wk2;
                    a[o] += rr[2*o+3]*wk3;
                    a[o] += rr[2*o+4]*wk4;
                }
            }
        }
        int oidx = codl*64 + coh*8 + owh*4;
        #pragma unroll
        for (int o=0;o<4;o++) sAcc[cic*128 + oidx + o] = a[o];
        __syncthreads();

        float s = 0.f;
        if (t < 128){
            #pragma unroll
            for (int ic=0;ic<12;ic++) s += sAcc[ic*128 + t];
            __stcg(&g_bufA[obase + t], s);
        }
        accL = s;
        float2 r = blockRed2(t<128 ? s : 0.f, t<128 ? s*s : 0.f, sred, t);
        if (t==0){ g_slots0[oc*16 + b*4 + odp] = r; }
    }
    gridBar(t, bid);

    // ================= 6x (input BN+ELU -> conv 8->8 k5 p2) =================
    for (int L=0; L<6; L++){
        int dir = L & 1;
        const float*  rin  = dir ? g_bufB   : g_bufA;
        float*        rout = dir ? g_bufA   : g_bufB;
        const float2* sinp = dir ? g_slots1 : g_slots0;
        float2*       sout = dir ? g_slots0 : g_slots1;
        const float*  gin  = (L==0) ? bn1_g : (bns_g + (L-1)*8);
        const float*  bin  = (L==0) ? bn1_b : (bns_b + (L-1)*8);
        const float*  w    = wS + L*8000;

        if (t < 8){
            float sx=0.f, sy=0.f;
            #pragma unroll
            for (int q=0;q<16;q++){
                float2 p = *(const float2*)&sinp[t*16+q];
                sx+=p.x; sy+=p.y;
            }
            float m  = sx*(1.f/2048.f);
            float vr = sy*(1.f/2048.f) - m*m;
            float sc = gin[t]*rsqrtf(vr + 1e-5f);
            sSc[t]=sc; sSh[t]=bin[t]-m*sc;
        }
        for (int i=t;i<1000;i+=384){
            int ic=i/125, r=i%125, kd=r/25, kh=(r%25)/5, kw=r%5;
            wsm[((ic*5+kd)*5+kh)*8 + kw] = w[oc*1000 + i];
        }
        __syncthreads();

        // batched interior fill (768 float4 items over 384 threads)
        {
            float4 vv[2]; bool ok[2]; int di[2];
            #pragma unroll
            for (int u=0;u<2;u++){
                int i = t + u*384;
                int half = i&1, h = (i>>1)&7, dd = (i>>4)%6, ic = i/96;
                int id = odp*2 - 2 + dd;
                ok[u] = (unsigned)id < 8u;
                di[u] = ic*864 + dd*144 + (h+2)*12 + 2 + half*4;
                if (ok[u])
                    vv[u] = __ldcg((const float4*)(rin + b*4096 + ic*512 + id*64 + h*8 + half*4));
            }
            #pragma unroll
            for (int u=0;u<2;u++){
                if (ok[u]){
                    int i = t + u*384;
                    int ic = i/96;
                    float sc = sSc[ic], sh = sSh[ic];
                    float* d = sIn + di[u];
                    d[0]=eluf(vv[u].x*sc+sh); d[1]=eluf(vv[u].y*sc+sh);
                    d[2]=eluf(vv[u].z*sc+sh); d[3]=eluf(vv[u].w*sc+sh);
                }
            }
        }
        __syncthreads();

        float a[4] = {0.f,0.f,0.f,0.f};
        if (cic < 8){   // 256 active threads
            const float* cb = sIn + cic*864;
            const float* wb = wsm + cic*200;
            #pragma unroll
            for (int kd=0;kd<5;kd++){
                #pragma unroll
                for (int kh=0;kh<5;kh++){
                    const float* row = cb + (codl+kd)*144 + (coh+kh)*12 + owh*4;
                    float4 r0 = *(const float4*)(row);
                    float4 r1 = *(const float4*)(row+4);
                    float rr[8] = {r0.x,r0.y,r0.z,r0.w, r1.x,r1.y,r1.z,r1.w};
                    const float* wp = wb + (kd*5+kh)*8;
                    float4 wv = *(const float4*)wp;
                    float wk4 = wp[4];
                    #pragma unroll
                    for (int o=0;o<4;o++){
                        a[o] += rr[o+0]*wv.x;
                        a[o] += rr[o+1]*wv.y;
                        a[o] += rr[o+2]*wv.z;
                        a[o] += rr[o+3]*wv.w;
                        a[o] += rr[o+4]*wk4;
                    }
                }
            }
            int oidx = codl*64 + coh*8 + owh*4;
            #pragma unroll
            for (int o=0;o<4;o++) sAcc[cic*128 + oidx + o] = a[o];
        }
        __syncthreads();

        float s = 0.f;
        if (t < 128){
            #pragma unroll
            for (int ic=0;ic<8;ic++) s += sAcc[ic*128 + t];
            __stcg(&rout[obase + t], s);
        }
        accL = s;
        float2 r = blockRed2(t<128 ? s : 0.f, t<128 ? s*s : 0.f, sred, t);
        if (t==0){ sout[oc*16 + b*4 + odp] = r; }
        gridBar(t, bid);
    }

    // ================= final BN+ELU from live accumulator ===================
    if (t < 128){
        float sx=0.f, sy=0.f;
        #pragma unroll
        for (int q=0;q<16;q++){
            float2 p = *(const float2*)&g_slots0[oc*16+q];
            sx+=p.x; sy+=p.y;
        }
        float m  = sx*(1.f/2048.f);
        float vr = sy*(1.f/2048.f) - m*m;
        float sc = bns_g[40+oc]*rsqrtf(vr + 1e-5f);
        float sh = bns_b[40+oc]-m*sc;
        outp[(b*8+oc)*512 + odp*128 + t] = eluf(accL*sc+sh);
    }
}

// ---------------------------------------------------------------------------
extern "C" void kernel_launch(void* const* d_in, const int* in_sizes, int n_in,
                              void* d_out, int out_size)
{
    const float* goals       = (const float*)d_in[0];
    const float* inputs      = (const float*)d_in[1];
    const float* backgrounds = (const float*)d_in[2];
    const float* W1 = (const float*)d_in[3];
    const float* b1 = (const float*)d_in[4];
    const float* W2 = (const float*)d_in[5];
    const float* b2 = (const float*)d_in[6];
    const float* W3 = (const float*)d_in[7];
    const float* b3 = (const float*)d_in[8];
    const float* conv1_w = (const float*)d_in[9];
    const float* bn1_g   = (const float*)d_in[11];
    const float* bn1_b   = (const float*)d_in[12];
    const float* convs_w = (const float*)d_in[13];
    const float* bns_g   = (const float*)d_in[15];
    const float* bns_b   = (const float*)d_in[16];
    float* out = (float*)d_out;

    void* gptr = nullptr;
    cudaGetSymbolAddress(&gptr, g_grid);
    cudaMemsetAsync(gptr, 0, GRIDN*sizeof(float));

    dim3 pg((PPC + 255)/256, 3);
    point_kernel<<<pg,256>>>(inputs, goals, backgrounds, W1,b1,W2,b2,W3,b3);

    conv_stack_kernel<<<128,384>>>(conv1_w, convs_w, bn1_g, bn1_b,
                                   bns_g, bns_b, out);
}